// round 15
// baseline (speedup 1.0000x reference)
#include <cuda_runtime.h>
#include <cuda_fp16.h>
#include <cstdint>

// out = relu( (S0@(x*sd0) + S1@(x*sd1) + S2@(x*sd2)) @ W )
// Big GEMM: M=8192, N=128, K=3*8192, fp16 operands, fp32 accum.
// Verified R5 structure: BM=64, BK=64, 8 warps 2m x 4n, 2 CTAs/SM.
// Single variable vs R5: NSLICE 7 -> 6 (768 CTAs of 64 k-tiles) to cut
// per-CTA prologue/epilogue overhead (R14 falsified the quantization model).

#define GN 8192
#define GD 128
#define BM 64
#define BK 64
#define NSTB 4
#define AWRD 36                      // A words (f16x2) per row: 32 + 4 pad
#define A_STG_W (BM * AWRD)          // 2304 words per A stage
#define B_STG_W (32 * 128)           // 4096 words per B stage (kpair x chan)
#define SMEM_MAIN ((NSTB * B_STG_W + 2 * A_STG_W) * 4)  // 83,968 B
#define NSLICE 6
#define KT_TOT 384                   // 3*8192/64

// Scratch (no allocation allowed)
__device__ __align__(16) __half g_Xt[3ull * GN * GD];        // 6 MB, tile-blocked
__device__ float g_P[(size_t)NSLICE * GN * GD];              // partials

__device__ __forceinline__ void cp_async16(void* smem_dst, const void* gsrc) {
    uint32_t s = (uint32_t)__cvta_generic_to_shared(smem_dst);
    asm volatile("cp.async.cg.shared.global [%0], [%1], 16;\n" ::"r"(s), "l"(gsrc));
}
__device__ __forceinline__ void cp_commit() {
    asm volatile("cp.async.commit_group;\n" ::);
}
template <int N>
__device__ __forceinline__ void cp_wait() {
    asm volatile("cp.async.wait_group %0;\n" ::"n"(N));
}

__device__ __forceinline__ void mma_f16(float d[4], const uint32_t a[4],
                                        const uint32_t b[2]) {
    asm volatile(
        "mma.sync.aligned.m16n8k16.row.col.f32.f16.f16.f32 "
        "{%0,%1,%2,%3}, {%4,%5,%6,%7}, {%8,%9}, {%0,%1,%2,%3};\n"
        : "+f"(d[0]), "+f"(d[1]), "+f"(d[2]), "+f"(d[3])
        : "r"(a[0]), "r"(a[1]), "r"(a[2]), "r"(a[3]), "r"(b[0]), "r"(b[1]));
}

__device__ __forceinline__ uint32_t pack_h2(float a, float b) {
    __half2 h = __floats2half2_rn(a, b);
    return *reinterpret_cast<uint32_t*>(&h);
}

// Kernel 1: pack B = fp16(x[k][c] * sd_s[c]) into tile-blocked XOR layout.
// Tile g (= s*128 + kt): 4096 f16x2 words,
//   word[kp*128 + (c ^ ((kp&3)<<3))] = { x[kt*64+2kp][c]*sd, x[kt*64+2kp+1][c]*sd }
__global__ __launch_bounds__(256) void prep_xt(const float* __restrict__ x,
                                               const float* __restrict__ sd0,
                                               const float* __restrict__ sd1,
                                               const float* __restrict__ sd2) {
    __shared__ float xs[64 * 128];
    __shared__ float sds[3][128];
    const int tid = threadIdx.x;
    const int kb = blockIdx.x * 64;

#pragma unroll
    for (int j = 0; j < 8; j++) {
        int idx = j * 256 + tid;
        ((float4*)xs)[idx] = ((const float4*)(x + (size_t)kb * GD))[idx];
    }
    if (tid < 128) {
        sds[0][tid] = sd0[tid];
        sds[1][tid] = sd1[tid];
        sds[2][tid] = sd2[tid];
    }
    __syncthreads();

    __half2* dst = (__half2*)g_Xt;
#pragma unroll
    for (int s = 0; s < 3; s++) {
        __half2* blk = dst + ((size_t)(s * 128 + blockIdx.x)) * 4096;
#pragma unroll
        for (int w16 = 0; w16 < 16; w16++) {
            int w = w16 * 256 + tid;
            int kp = w >> 7;
            int c = (w & 127) ^ ((kp & 3) << 3);
            float sc = sds[s][c];
            blk[w] = __floats2half2_rn(xs[(2 * kp) * 128 + c] * sc,
                                       xs[(2 * kp + 1) * 128 + c] * sc);
        }
    }
}

// Kernel 2: main GEMM. grid 768 = 128 row-blocks x 6 slices, 2 CTAs/SM.
// 8 warps in 2(m) x 4(n); warp tile 32x32; mma.m16n8k16 fp16 -> fp32.
// A: LDG fp32 -> cvt f16x2 in regs -> STS (2-stage, prefetch 2 ahead).
// B: cp.async fp16 from pre-packed g_Xt (4-stage ring).
__global__ __launch_bounds__(256, 2) void main_gemm(const float* __restrict__ S0,
                                                    const float* __restrict__ S1,
                                                    const float* __restrict__ S2) {
    extern __shared__ uint32_t smw[];
    uint32_t* Bs = smw;                      // NSTB * B_STG_W
    uint32_t* As = smw + NSTB * B_STG_W;     // 2 * A_STG_W

    const int tid = threadIdx.x;
    const int slice = blockIdx.x % NSLICE;
    const int row_blk = blockIdx.x / NSLICE;
    const int block_row = row_blk * BM;
    const int kt_begin = (slice * KT_TOT) / NSLICE;
    const int KT = ((slice + 1) * KT_TOT) / NSLICE - kt_begin;

    const int wid = tid >> 5, lane = tid & 31;
    const int warp_m = wid & 1, warp_n = wid >> 1;
    const int gid = lane >> 2, tig = lane & 3;
    const int m_base = warp_m * 32, n_base = warp_n * 32;

    float acc[2][4][4];
#pragma unroll
    for (int mi = 0; mi < 2; mi++)
#pragma unroll
        for (int ni = 0; ni < 4; ni++)
#pragma unroll
            for (int q = 0; q < 4; q++) acc[mi][ni][q] = 0.f;

    uint32_t regA[8];

    auto srcS = [&](int g) -> const float* {
        int s = g >> 7;
        const float* p = (s == 0) ? S0 : (s == 1) ? S1 : S2;
        return p + (size_t)block_row * GN + ((g & 127) << 6);
    };

    auto issueB = [&](int stage, int kt) {
        const char* src =
            (const char*)g_Xt + (size_t)(kt_begin + kt) * (64 * GD * 2);
        char* dst = (char*)(Bs + stage * B_STG_W);
#pragma unroll
        for (int j = 0; j < 4; j++) {
            int idx = j * 256 + tid;
            cp_async16(dst + idx * 16, src + idx * 16);
        }
    };

    // 64 rows x 16 float4 = 1024 float4; 4/thread -> 8 packed u32
    auto ldgA = [&](int kt) {
        const float* Ag = srcS(kt_begin + kt);
#pragma unroll
        for (int j = 0; j < 4; j++) {
            int idx = j * 256 + tid;
            int r = idx >> 4;
            int c4 = (idx & 15) * 4;
            float4 v = *(const float4*)(Ag + (size_t)r * GN + c4);
            regA[j * 2 + 0] = pack_h2(v.x, v.y);
            regA[j * 2 + 1] = pack_h2(v.z, v.w);
        }
    };

    auto stsA = [&](int buf) {
        uint32_t* aw = As + buf * A_STG_W;
#pragma unroll
        for (int j = 0; j < 4; j++) {
            int idx = j * 256 + tid;
            int r = idx >> 4;
            int q = (idx & 15) * 2;
            uint2 w;
            w.x = regA[j * 2 + 0];
            w.y = regA[j * 2 + 1];
            *(uint2*)&aw[r * AWRD + q] = w;
        }
    };

    auto compute = [&](int kt) {
        const uint32_t* aw = As + (kt & 1) * A_STG_W;
        const uint32_t* bw = Bs + (kt & 3) * B_STG_W;
#pragma unroll
        for (int kk = 0; kk < 4; kk++) {
            const int kp0 = kk * 8;
            uint32_t a[2][4];
#pragma unroll
            for (int mi = 0; mi < 2; mi++) {
                int r = m_base + mi * 16 + gid;
                a[mi][0] = aw[r * AWRD + kp0 + tig];
                a[mi][1] = aw[(r + 8) * AWRD + kp0 + tig];
                a[mi][2] = aw[r * AWRD + kp0 + 4 + tig];
                a[mi][3] = aw[(r + 8) * AWRD + kp0 + 4 + tig];
            }
#pragma unroll
            for (int ni = 0; ni < 4; ni++) {
                int cx = (n_base + ni * 8 + gid) ^ (tig << 3);
                uint32_t b[2];
                b[0] = bw[(kp0 + tig) * 128 + cx];
                b[1] = bw[(kp0 + tig + 4) * 128 + cx];
#pragma unroll
                for (int mi = 0; mi < 2; mi++) mma_f16(acc[mi][ni], a[mi], b);
            }
        }
    };

    // prologue
    issueB(0, 0);
    cp_commit();
    issueB(1, 1);
    cp_commit();
    issueB(2, 2);
    cp_commit();
    ldgA(0);
    stsA(0);
    ldgA(1);  // regA now holds tile 1

    for (int kt = 0; kt < KT; kt++) {
        cp_wait<NSTB - 2>();
        __syncthreads();
        if (kt + 3 < KT) issueB((kt + 3) & 3, kt + 3);
        cp_commit();
        if (kt + 1 < KT) stsA((kt + 1) & 1);
        if (kt + 2 < KT) ldgA(kt + 2);
        compute(kt);
    }

    // store partial sums (fp32)
    float* P = g_P + (size_t)slice * GN * GD;
#pragma unroll
    for (int mi = 0; mi < 2; mi++) {
#pragma unroll
        for (int ni = 0; ni < 4; ni++) {
            int r = block_row + m_base + mi * 16 + gid;
            int c = n_base + ni * 8 + tig * 2;
            *(float2*)&P[(size_t)r * GD + c] =
                make_float2(acc[mi][ni][0], acc[mi][ni][1]);
            *(float2*)&P[(size_t)(r + 8) * GD + c] =
                make_float2(acc[mi][ni][2], acc[mi][ni][3]);
        }
    }
}

// Kernel 3: out = relu( (sum_slices P) @ W ).  grid 256 (32 rows each).
#define SMEM_FIN ((128 * 132 + 32 * 128) * 4)  // 83,968 B
__global__ __launch_bounds__(256, 2) void proj_relu(const float* __restrict__ W,
                                                    float* __restrict__ out) {
    extern __shared__ float fs[];
    float* Ws = fs;               // [128][132]
    float* agg = fs + 128 * 132;  // [32][128]
    const int tid = threadIdx.x;
    const int row0 = blockIdx.x * 32;

#pragma unroll
    for (int j = 0; j < 16; j++) {
        int idx = j * 256 + tid;
        int r = idx >> 5;
        int c4 = (idx & 31) * 4;
        *(float4*)&Ws[r * 132 + c4] = *(const float4*)&W[r * GD + c4];
    }
#pragma unroll
    for (int j = 0; j < 4; j++) {
        int idx = j * 256 + tid;
        int r = idx >> 5;
        int c4 = (idx & 31) * 4;
        float4 s = make_float4(0.f, 0.f, 0.f, 0.f);
#pragma unroll
        for (int sl = 0; sl < NSLICE; sl++) {
            float4 v = *(const float4*)&g_P[((size_t)sl * GN + row0 + r) * GD + c4];
            s.x += v.x; s.y += v.y; s.z += v.z; s.w += v.w;
        }
        *(float4*)&agg[r * 128 + c4] = s;
    }
    __syncthreads();

    const int tx = tid & 15;
    const int ty = tid >> 4;
    float acc[2][8];
#pragma unroll
    for (int i = 0; i < 2; i++)
#pragma unroll
        for (int j = 0; j < 8; j++) acc[i][j] = 0.f;

#pragma unroll 4
    for (int c = 0; c < 128; c++) {
        float a0 = agg[(ty * 2) * 128 + c];
        float a1 = agg[(ty * 2 + 1) * 128 + c];
        float w[8];
        *(float4*)&w[0] = *(float4*)&Ws[c * 132 + tx * 8];
        *(float4*)&w[4] = *(float4*)&Ws[c * 132 + tx * 8 + 4];
#pragma unroll
        for (int j = 0; j < 8; j++) {
            acc[0][j] = fmaf(a0, w[j], acc[0][j]);
            acc[1][j] = fmaf(a1, w[j], acc[1][j]);
        }
    }

#pragma unroll
    for (int i = 0; i < 2; i++) {
        float* dst = &out[(size_t)(row0 + ty * 2 + i) * GD + tx * 8];
        float4 v0, v1;
        v0.x = fmaxf(acc[i][0], 0.f);
        v0.y = fmaxf(acc[i][1], 0.f);
        v0.z = fmaxf(acc[i][2], 0.f);
        v0.w = fmaxf(acc[i][3], 0.f);
        v1.x = fmaxf(acc[i][4], 0.f);
        v1.y = fmaxf(acc[i][5], 0.f);
        v1.z = fmaxf(acc[i][6], 0.f);
        v1.w = fmaxf(acc[i][7], 0.f);
        *(float4*)&dst[0] = v0;
        *(float4*)&dst[4] = v1;
    }
}

extern "C" void kernel_launch(void* const* d_in, const int* in_sizes, int n_in,
                              void* d_out, int out_size) {
    const float* x = (const float*)d_in[0];
    const float* S0 = (const float*)d_in[1];
    const float* S1 = (const float*)d_in[2];
    const float* S2 = (const float*)d_in[3];
    const float* W = (const float*)d_in[4];
    const float* sd0 = (const float*)d_in[5];
    const float* sd1 = (const float*)d_in[6];
    const float* sd2 = (const float*)d_in[7];
    float* out = (float*)d_out;

    cudaFuncSetAttribute(main_gemm, cudaFuncAttributeMaxDynamicSharedMemorySize,
                         SMEM_MAIN);
    cudaFuncSetAttribute(proj_relu, cudaFuncAttributeMaxDynamicSharedMemorySize,
                         SMEM_FIN);

    prep_xt<<<GN / 64, 256>>>(x, sd0, sd1, sd2);
    main_gemm<<<128 * NSLICE, 256, SMEM_MAIN>>>(S0, S1, S2);
    proj_relu<<<GN / 32, 256, SMEM_FIN>>>(W, out);
}

// round 16
// speedup vs baseline: 1.4052x; 1.4052x over previous
#include <cuda_runtime.h>
#include <cuda_fp16.h>
#include <cstdint>

// ---------------------------------------------------------------------------
// out = relu( (S0@(x*sd0) + S1@(x*sd1) + S2@(x*sd2)) @ W )
// Big GEMM: M=8192, N=128 (channels), K=3*8192, fp16 operands, fp32 accum.
// 896 CTAs = 128 row-blocks x 7 k-slices (~55 tiles of BK=64 each).
// Byte-identical re-run of the Round-5 kernel (213.2 us) to re-anchor
// against suspected bench-environment drift.
// ---------------------------------------------------------------------------
#define GN 8192
#define GD 128
#define BM 64
#define BK 64
#define NSTB 4
#define AWRD 36                      // A words (f16x2) per row: 32 + 4 pad
#define A_STG_W (BM * AWRD)          // 2304 words per A stage
#define B_STG_W (32 * 128)           // 4096 words per B stage (kpair x chan)
#define SMEM_MAIN ((NSTB * B_STG_W + 2 * A_STG_W) * 4)  // 83,968 B
#define NSLICE 7
#define KT_TOT 384                   // 3*8192/64

// Scratch (no allocation allowed)
__device__ __align__(16) __half g_Xt[3ull * GN * GD];        // 6 MB, tile-blocked
__device__ float g_P[(size_t)NSLICE * GN * GD];              // partials

// ---------------------------------------------------------------------------
__device__ __forceinline__ void cp_async16(void* smem_dst, const void* gsrc) {
    uint32_t s = (uint32_t)__cvta_generic_to_shared(smem_dst);
    asm volatile("cp.async.cg.shared.global [%0], [%1], 16;\n" ::"r"(s), "l"(gsrc));
}
__device__ __forceinline__ void cp_commit() {
    asm volatile("cp.async.commit_group;\n" ::);
}
template <int N>
__device__ __forceinline__ void cp_wait() {
    asm volatile("cp.async.wait_group %0;\n" ::"n"(N));
}

__device__ __forceinline__ void mma_f16(float d[4], const uint32_t a[4],
                                        const uint32_t b[2]) {
    asm volatile(
        "mma.sync.aligned.m16n8k16.row.col.f32.f16.f16.f32 "
        "{%0,%1,%2,%3}, {%4,%5,%6,%7}, {%8,%9}, {%0,%1,%2,%3};\n"
        : "+f"(d[0]), "+f"(d[1]), "+f"(d[2]), "+f"(d[3])
        : "r"(a[0]), "r"(a[1]), "r"(a[2]), "r"(a[3]), "r"(b[0]), "r"(b[1]));
}

__device__ __forceinline__ uint32_t pack_h2(float a, float b) {
    __half2 h = __floats2half2_rn(a, b);
    return *reinterpret_cast<uint32_t*>(&h);
}

// ---------------------------------------------------------------------------
// Kernel 1: pack B = fp16(x[k][c] * sd_s[c]) into tile-blocked XOR layout.
// Tile g (= s*128 + kt) is an 8 KB contiguous block of 4096 f16x2 words:
//   word[kp*128 + (c ^ ((kp&3)<<3))] = { x[kt*64+2kp][c]*sd, x[kt*64+2kp+1][c]*sd }
// grid 128 (one per kt), 256 threads.
// ---------------------------------------------------------------------------
__global__ __launch_bounds__(256) void prep_xt(const float* __restrict__ x,
                                               const float* __restrict__ sd0,
                                               const float* __restrict__ sd1,
                                               const float* __restrict__ sd2) {
    __shared__ float xs[64 * 128];
    __shared__ float sds[3][128];
    const int tid = threadIdx.x;
    const int kb = blockIdx.x * 64;

#pragma unroll
    for (int j = 0; j < 8; j++) {
        int idx = j * 256 + tid;
        ((float4*)xs)[idx] = ((const float4*)(x + (size_t)kb * GD))[idx];
    }
    if (tid < 128) {
        sds[0][tid] = sd0[tid];
        sds[1][tid] = sd1[tid];
        sds[2][tid] = sd2[tid];
    }
    __syncthreads();

    __half2* dst = (__half2*)g_Xt;
#pragma unroll
    for (int s = 0; s < 3; s++) {
        __half2* blk = dst + ((size_t)(s * 128 + blockIdx.x)) * 4096;
#pragma unroll
        for (int w16 = 0; w16 < 16; w16++) {
            int w = w16 * 256 + tid;
            int kp = w >> 7;
            int c = (w & 127) ^ ((kp & 3) << 3);
            float sc = sds[s][c];
            blk[w] = __floats2half2_rn(xs[(2 * kp) * 128 + c] * sc,
                                       xs[(2 * kp + 1) * 128 + c] * sc);
        }
    }
}

// ---------------------------------------------------------------------------
// Kernel 2: main GEMM. grid 896 = 128 row-blocks x 7 slices, 2 CTAs/SM.
// 8 warps in 2(m) x 4(n); warp tile 32x32; mma.m16n8k16 fp16 -> fp32.
// A: LDG fp32 -> cvt f16x2 -> STS (2-stage smem, prefetch 2 tiles ahead).
// B: cp.async fp16 from pre-packed g_Xt (4-stage).
// ---------------------------------------------------------------------------
__global__ __launch_bounds__(256, 2) void main_gemm(const float* __restrict__ S0,
                                                    const float* __restrict__ S1,
                                                    const float* __restrict__ S2) {
    extern __shared__ uint32_t smw[];
    uint32_t* Bs = smw;                      // NSTB * B_STG_W
    uint32_t* As = smw + NSTB * B_STG_W;     // 2 * A_STG_W

    const int tid = threadIdx.x;
    const int slice = blockIdx.x % NSLICE;
    const int row_blk = blockIdx.x / NSLICE;
    const int block_row = row_blk * BM;
    const int kt_begin = (slice * KT_TOT) / NSLICE;
    const int KT = ((slice + 1) * KT_TOT) / NSLICE - kt_begin;

    const int wid = tid >> 5, lane = tid & 31;
    const int warp_m = wid & 1, warp_n = wid >> 1;
    const int gid = lane >> 2, tig = lane & 3;
    const int m_base = warp_m * 32, n_base = warp_n * 32;

    float acc[2][4][4];
#pragma unroll
    for (int mi = 0; mi < 2; mi++)
#pragma unroll
        for (int ni = 0; ni < 4; ni++)
#pragma unroll
            for (int q = 0; q < 4; q++) acc[mi][ni][q] = 0.f;

    float regA[16];

    auto srcS = [&](int g) -> const float* {
        int s = g >> 7;
        const float* p = (s == 0) ? S0 : (s == 1) ? S1 : S2;
        return p + (size_t)block_row * GN + ((g & 127) << 6);
    };

    auto issueB = [&](int stage, int kt) {
        const char* src =
            (const char*)g_Xt + (size_t)(kt_begin + kt) * (64 * GD * 2);
        char* dst = (char*)(Bs + stage * B_STG_W);
#pragma unroll
        for (int j = 0; j < 4; j++) {
            int idx = j * 256 + tid;
            cp_async16(dst + idx * 16, src + idx * 16);
        }
    };

    auto ldgA = [&](int kt) {
        const float* Ag = srcS(kt_begin + kt);
#pragma unroll
        for (int j = 0; j < 4; j++) {
            int idx = j * 256 + tid;
            int r = idx >> 4;
            int c4 = (idx & 15) * 4;
            float4 v = *(const float4*)(Ag + (size_t)r * GN + c4);
            regA[j * 4 + 0] = v.x;
            regA[j * 4 + 1] = v.y;
            regA[j * 4 + 2] = v.z;
            regA[j * 4 + 3] = v.w;
        }
    };

    auto stsA = [&](int buf) {
        uint32_t* aw = As + buf * A_STG_W;
#pragma unroll
        for (int j = 0; j < 4; j++) {
            int idx = j * 256 + tid;
            int r = idx >> 4;
            int q = (idx & 15) * 2;  // kpair base
            uint2 w;
            w.x = pack_h2(regA[j * 4 + 0], regA[j * 4 + 1]);
            w.y = pack_h2(regA[j * 4 + 2], regA[j * 4 + 3]);
            *(uint2*)&aw[r * AWRD + q] = w;
        }
    };

    auto compute = [&](int kt) {
        const uint32_t* aw = As + (kt & 1) * A_STG_W;
        const uint32_t* bw = Bs + (kt & 3) * B_STG_W;
#pragma unroll
        for (int kk = 0; kk < 4; kk++) {
            const int kp0 = kk * 8;
            uint32_t a[2][4];
#pragma unroll
            for (int mi = 0; mi < 2; mi++) {
                int r = m_base + mi * 16 + gid;
                a[mi][0] = aw[r * AWRD + kp0 + tig];
                a[mi][1] = aw[(r + 8) * AWRD + kp0 + tig];
                a[mi][2] = aw[r * AWRD + kp0 + 4 + tig];
                a[mi][3] = aw[(r + 8) * AWRD + kp0 + 4 + tig];
            }
            uint32_t b[4][2];
#pragma unroll
            for (int ni = 0; ni < 4; ni++) {
                int cx = (n_base + ni * 8 + gid) ^ (tig << 3);
                b[ni][0] = bw[(kp0 + tig) * 128 + cx];
                b[ni][1] = bw[(kp0 + tig + 4) * 128 + cx];
            }
#pragma unroll
            for (int mi = 0; mi < 2; mi++)
#pragma unroll
                for (int ni = 0; ni < 4; ni++)
                    mma_f16(acc[mi][ni], a[mi], b[ni]);
        }
    };

    // prologue
    issueB(0, 0);
    cp_commit();
    issueB(1, 1);
    cp_commit();
    issueB(2, 2);
    cp_commit();
    ldgA(0);
    stsA(0);
    ldgA(1);  // regA now holds tile 1

    for (int kt = 0; kt < KT; kt++) {
        cp_wait<NSTB - 2>();
        __syncthreads();
        if (kt + 3 < KT) issueB((kt + 3) & 3, kt + 3);
        cp_commit();
        if (kt + 1 < KT) stsA((kt + 1) & 1);
        if (kt + 2 < KT) ldgA(kt + 2);
        compute(kt);
    }

    // store partial sums (fp32), no relu yet
    float* P = g_P + (size_t)slice * GN * GD;
#pragma unroll
    for (int mi = 0; mi < 2; mi++) {
#pragma unroll
        for (int ni = 0; ni < 4; ni++) {
            int r = block_row + m_base + mi * 16 + gid;
            int c = n_base + ni * 8 + tig * 2;
            *(float2*)&P[(size_t)r * GD + c] =
                make_float2(acc[mi][ni][0], acc[mi][ni][1]);
            *(float2*)&P[(size_t)(r + 8) * GD + c] =
                make_float2(acc[mi][ni][2], acc[mi][ni][3]);
        }
    }
}

// ---------------------------------------------------------------------------
// Kernel 3: out = relu( (sum_slices P) @ W ).  grid 256 (32 rows each).
// ---------------------------------------------------------------------------
#define SMEM_FIN ((128 * 132 + 32 * 128) * 4)  // 83,968 B
__global__ __launch_bounds__(256, 2) void proj_relu(const float* __restrict__ W,
                                                    float* __restrict__ out) {
    extern __shared__ float fs[];
    float* Ws = fs;               // [128][132]
    float* agg = fs + 128 * 132;  // [32][128]
    const int tid = threadIdx.x;
    const int row0 = blockIdx.x * 32;

#pragma unroll
    for (int j = 0; j < 16; j++) {
        int idx = j * 256 + tid;
        int r = idx >> 5;
        int c4 = (idx & 31) * 4;
        *(float4*)&Ws[r * 132 + c4] = *(const float4*)&W[r * GD + c4];
    }
#pragma unroll
    for (int j = 0; j < 4; j++) {
        int idx = j * 256 + tid;
        int r = idx >> 5;
        int c4 = (idx & 31) * 4;
        float4 s = make_float4(0.f, 0.f, 0.f, 0.f);
#pragma unroll
        for (int sl = 0; sl < NSLICE; sl++) {
            float4 v = *(const float4*)&g_P[((size_t)sl * GN + row0 + r) * GD + c4];
            s.x += v.x; s.y += v.y; s.z += v.z; s.w += v.w;
        }
        *(float4*)&agg[r * 128 + c4] = s;
    }
    __syncthreads();

    const int tx = tid & 15;  // cols tx*8..+7
    const int ty = tid >> 4;  // rows ty*2..+1
    float acc[2][8];
#pragma unroll
    for (int i = 0; i < 2; i++)
#pragma unroll
        for (int j = 0; j < 8; j++) acc[i][j] = 0.f;

#pragma unroll 4
    for (int c = 0; c < 128; c++) {
        float a0 = agg[(ty * 2) * 128 + c];
        float a1 = agg[(ty * 2 + 1) * 128 + c];
        float w[8];
        *(float4*)&w[0] = *(float4*)&Ws[c * 132 + tx * 8];
        *(float4*)&w[4] = *(float4*)&Ws[c * 132 + tx * 8 + 4];
#pragma unroll
        for (int j = 0; j < 8; j++) {
            acc[0][j] = fmaf(a0, w[j], acc[0][j]);
            acc[1][j] = fmaf(a1, w[j], acc[1][j]);
        }
    }

#pragma unroll
    for (int i = 0; i < 2; i++) {
        float* dst = &out[(size_t)(row0 + ty * 2 + i) * GD + tx * 8];
        float4 v0, v1;
        v0.x = fmaxf(acc[i][0], 0.f);
        v0.y = fmaxf(acc[i][1], 0.f);
        v0.z = fmaxf(acc[i][2], 0.f);
        v0.w = fmaxf(acc[i][3], 0.f);
        v1.x = fmaxf(acc[i][4], 0.f);
        v1.y = fmaxf(acc[i][5], 0.f);
        v1.z = fmaxf(acc[i][6], 0.f);
        v1.w = fmaxf(acc[i][7], 0.f);
        *(float4*)&dst[0] = v0;
        *(float4*)&dst[4] = v1;
    }
}

// ---------------------------------------------------------------------------
extern "C" void kernel_launch(void* const* d_in, const int* in_sizes, int n_in,
                              void* d_out, int out_size) {
    const float* x = (const float*)d_in[0];
    const float* S0 = (const float*)d_in[1];
    const float* S1 = (const float*)d_in[2];
    const float* S2 = (const float*)d_in[3];
    const float* W = (const float*)d_in[4];
    const float* sd0 = (const float*)d_in[5];
    const float* sd1 = (const float*)d_in[6];
    const float* sd2 = (const float*)d_in[7];
    float* out = (float*)d_out;

    cudaFuncSetAttribute(main_gemm, cudaFuncAttributeMaxDynamicSharedMemorySize,
                         SMEM_MAIN);
    cudaFuncSetAttribute(proj_relu, cudaFuncAttributeMaxDynamicSharedMemorySize,
                         SMEM_FIN);

    prep_xt<<<GN / 64, 256>>>(x, sd0, sd1, sd2);
    main_gemm<<<128 * NSLICE, 256, SMEM_MAIN>>>(S0, S1, S2);
    proj_relu<<<GN / 32, 256, SMEM_FIN>>>(W, out);
}